// round 3
// baseline (speedup 1.0000x reference)
#include <cuda_runtime.h>

// LocalAttention2D: windowed MHSA (Swin-style, no shift)
// B=8, H=W=192, C=256, WS=8, heads=8, d=32 -> 4608 windows of 64 tokens.
// One CTA per window, 256 threads, fully fused in shared memory, fp32.

#define NWIN_TOTAL 4608
#define NH 8

// shared memory layout (floats)
//  sXT   [256][64]  x window transposed (k-major)          16384
//  sOutT [256][64]  attention output transposed             16384
//  sW    up to [16][256] / [32][96] staged weight tile       4096
//  sQT   [32][64]                                            2048
//  sKT   [32][64]                                            2048
//  sV    [64][32]                                            2048
//  sS    [64][68]   scores (padded stride)                   4352
//  sPT   [64][68]   softmax probs transposed                 4352
static constexpr int SMEM_FLOATS = 16384 + 16384 + 4096 + 2048 + 2048 + 2048 + 4352 + 4352;
static constexpr int SMEM_BYTES  = SMEM_FLOATS * 4;   // 206848 B  (< 227KB sm_100a opt-in cap)

__global__ __launch_bounds__(256, 1)
void win_mhsa_fp32_kernel(const float* __restrict__ x,
                          const float* __restrict__ w_qkv,
                          const float* __restrict__ b_qkv,
                          const float* __restrict__ w_proj,
                          const float* __restrict__ b_proj,
                          float* __restrict__ out)
{
    extern __shared__ float sm[];
    float* sXT   = sm;                       // [256][64]
    float* sOutT = sXT + 16384;              // [256][64]
    float* sW    = sOutT + 16384;            // staged W tile
    float* sQT   = sW + 4096;                // [32][64]
    float* sKT   = sQT + 2048;               // [32][64]
    float* sV    = sKT + 2048;               // [64][32]
    float* sS    = sV + 2048;                // [64][68]
    float* sPT   = sS + 64 * 68;             // [64][68]

    const int tid = threadIdx.x;
    const int win = blockIdx.x;
    const int b   = win / 576;               // 24*24 windows per batch
    const int wh  = (win % 576) / 24;
    const int ww  = win % 24;

    // ---------------- load X window, transposed: sXT[k][t] ----------------
    {
        const int t = tid >> 2;              // token 0..63
        const int p = tid & 3;               // quarter of the channel dim
        const long long roff =
            (((long long)(b * 192 + wh * 8 + (t >> 3))) * 192 + (ww * 8 + (t & 7))) * 256;
        const float4* gx = reinterpret_cast<const float4*>(x + roff);
        #pragma unroll
        for (int u = 0; u < 16; u++) {
            const int c4 = p * 16 + u;
            const float4 v = __ldg(&gx[c4]);
            const int c = c4 * 4;
            sXT[(c + 0) * 64 + t] = v.x;
            sXT[(c + 1) * 64 + t] = v.y;
            sXT[(c + 2) * 64 + t] = v.z;
            sXT[(c + 3) * 64 + t] = v.w;
        }
    }
    __syncthreads();

    const int tg = tid >> 4;                 // 0..15 -> 4 tokens each
    const int cg = tid & 15;                 // 0..15
    const int t0 = tg * 4;
    const float QSCALE = 0.17677669529663689f;  // 32^-0.5

    for (int h = 0; h < NH; h++) {
        // ============ GEMM1: [64 tok] x [96 qkv cols] x [K=256] ============
        float acc[4][6];
        #pragma unroll
        for (int m = 0; m < 4; m++)
            #pragma unroll
            for (int n = 0; n < 6; n++) acc[m][n] = 0.0f;

        // staged W tile: sW[kk][cp], kk in 0..31, cp in 0..95
        // global rows: cp<32 -> Q row h*32+cp ; 32..63 -> K (+256) ; 64..95 -> V (+512)
        const int f0 = tid, f1 = tid + 256, f2 = tid + 512;   // f4 ids (768 total)
        auto wqkv_f4 = [&](int fi, int kc) -> float4 {
            const int cp = fi >> 3;          // 0..95
            const int k4 = fi & 7;           // f4 within 32-wide k chunk
            const int grow = (cp >> 5) * 256 + h * 32 + (cp & 31);
            return __ldg(reinterpret_cast<const float4*>(w_qkv) + grow * 64 + kc * 8 + k4);
        };
        float4 p0 = wqkv_f4(f0, 0), p1 = wqkv_f4(f1, 0), p2 = wqkv_f4(f2, 0);

        for (int kc = 0; kc < 8; kc++) {
            // store staged tile (transpose to k-major)
            {
                const int cps[3] = { f0 >> 3, f1 >> 3, f2 >> 3 };
                const int kks[3] = { (f0 & 7) * 4, (f1 & 7) * 4, (f2 & 7) * 4 };
                const float4 ps[3] = { p0, p1, p2 };
                #pragma unroll
                for (int r = 0; r < 3; r++) {
                    sW[(kks[r] + 0) * 96 + cps[r]] = ps[r].x;
                    sW[(kks[r] + 1) * 96 + cps[r]] = ps[r].y;
                    sW[(kks[r] + 2) * 96 + cps[r]] = ps[r].z;
                    sW[(kks[r] + 3) * 96 + cps[r]] = ps[r].w;
                }
            }
            __syncthreads();
            if (kc < 7) { p0 = wqkv_f4(f0, kc + 1); p1 = wqkv_f4(f1, kc + 1); p2 = wqkv_f4(f2, kc + 1); }

            const float* xbase = &sXT[kc * 32 * 64 + t0];
            const float* wbase = &sW[cg * 6];
            #pragma unroll
            for (int kk = 0; kk < 32; kk++) {
                const float4 a  = *reinterpret_cast<const float4*>(xbase + kk * 64);
                const float2 bA = *reinterpret_cast<const float2*>(wbase + kk * 96);
                const float2 bB = *reinterpret_cast<const float2*>(wbase + kk * 96 + 2);
                const float2 bC = *reinterpret_cast<const float2*>(wbase + kk * 96 + 4);
                const float av[4] = { a.x, a.y, a.z, a.w };
                const float bv[6] = { bA.x, bA.y, bB.x, bB.y, bC.x, bC.y };
                #pragma unroll
                for (int m = 0; m < 4; m++)
                    #pragma unroll
                    for (int n = 0; n < 6; n++)
                        acc[m][n] += av[m] * bv[n];
            }
            __syncthreads();
        }

        // scatter q/k/v (+bias) into attention layouts
        {
            float biasv[6];
            #pragma unroll
            for (int n = 0; n < 6; n++) {
                const int cp = cg * 6 + n;
                biasv[n] = __ldg(&b_qkv[(cp >> 5) * 256 + h * 32 + (cp & 31)]);
            }
            #pragma unroll
            for (int n = 0; n < 6; n++) {
                const int cp   = cg * 6 + n;
                const int kind = cp >> 5;        // 0=q 1=k 2=v
                const int dd   = cp & 31;
                #pragma unroll
                for (int m = 0; m < 4; m++) {
                    const float v = acc[m][n] + biasv[n];
                    const int t = t0 + m;
                    if (kind == 0)      sQT[dd * 64 + t] = v * QSCALE;
                    else if (kind == 1) sKT[dd * 64 + t] = v;
                    else                sV[t * 32 + dd]  = v;
                }
            }
        }
        __syncthreads();

        // ============ S = (Q*scale) K^T : [64][64], k=d=32 ============
        {
            float sacc[4][4];
            #pragma unroll
            for (int m = 0; m < 4; m++)
                #pragma unroll
                for (int n = 0; n < 4; n++) sacc[m][n] = 0.0f;
            const int j0 = cg * 4;
            #pragma unroll
            for (int d = 0; d < 32; d++) {
                const float4 qa = *reinterpret_cast<const float4*>(&sQT[d * 64 + t0]);
                const float4 kb = *reinterpret_cast<const float4*>(&sKT[d * 64 + j0]);
                const float qv[4] = { qa.x, qa.y, qa.z, qa.w };
                const float kv[4] = { kb.x, kb.y, kb.z, kb.w };
                #pragma unroll
                for (int m = 0; m < 4; m++)
                    #pragma unroll
                    for (int n = 0; n < 4; n++)
                        sacc[m][n] += qv[m] * kv[n];
            }
            #pragma unroll
            for (int m = 0; m < 4; m++)
                *reinterpret_cast<float4*>(&sS[(t0 + m) * 68 + j0]) =
                    make_float4(sacc[m][0], sacc[m][1], sacc[m][2], sacc[m][3]);
        }
        __syncthreads();

        // ============ softmax rows (4 lanes per row) -> sPT[j][i] ============
        {
            const int r = tid >> 2;
            const int p = tid & 3;
            float v[16];
            const float* row = &sS[r * 68 + p * 16];
            #pragma unroll
            for (int u = 0; u < 4; u++) {
                const float4 f = *reinterpret_cast<const float4*>(row + u * 4);
                v[u * 4 + 0] = f.x; v[u * 4 + 1] = f.y;
                v[u * 4 + 2] = f.z; v[u * 4 + 3] = f.w;
            }
            float mx = v[0];
            #pragma unroll
            for (int i = 1; i < 16; i++) mx = fmaxf(mx, v[i]);
            mx = fmaxf(mx, __shfl_xor_sync(0xffffffffu, mx, 1));
            mx = fmaxf(mx, __shfl_xor_sync(0xffffffffu, mx, 2));
            float sum = 0.0f;
            #pragma unroll
            for (int i = 0; i < 16; i++) { v[i] = __expf(v[i] - mx); sum += v[i]; }
            sum += __shfl_xor_sync(0xffffffffu, sum, 1);
            sum += __shfl_xor_sync(0xffffffffu, sum, 2);
            const float inv = 1.0f / sum;
            #pragma unroll
            for (int i = 0; i < 16; i++) sPT[(p * 16 + i) * 68 + r] = v[i] * inv;
        }
        __syncthreads();

        // ============ O = P V : [64][32], k=64 ============
        {
            float oacc[4][2];
            #pragma unroll
            for (int m = 0; m < 4; m++) { oacc[m][0] = 0.0f; oacc[m][1] = 0.0f; }
            const int d0 = cg * 2;
            #pragma unroll 8
            for (int j = 0; j < 64; j++) {
                const float4 pa = *reinterpret_cast<const float4*>(&sPT[j * 68 + t0]);
                const float2 vb = *reinterpret_cast<const float2*>(&sV[j * 32 + d0]);
                const float pv[4] = { pa.x, pa.y, pa.z, pa.w };
                #pragma unroll
                for (int m = 0; m < 4; m++) {
                    oacc[m][0] += pv[m] * vb.x;
                    oacc[m][1] += pv[m] * vb.y;
                }
            }
            #pragma unroll
            for (int m = 0; m < 4; m++) {
                sOutT[(h * 32 + d0 + 0) * 64 + t0 + m] = oacc[m][0];
                sOutT[(h * 32 + d0 + 1) * 64 + t0 + m] = oacc[m][1];
            }
        }
        __syncthreads();
    } // heads

    // ============ proj: Y = O @ Wproj^T + b : [64][256], K=256 ============
    {
        float pacc[4][16];
        #pragma unroll
        for (int m = 0; m < 4; m++)
            #pragma unroll
            for (int n = 0; n < 16; n++) pacc[m][n] = 0.0f;

        const int g0 = tid, g1 = tid + 256, g2 = tid + 512, g3 = tid + 768;  // 1024 f4 / tile
        auto wproj_f4 = [&](int fi, int kc) -> float4 {
            const int c  = fi >> 2;          // 0..255 output col
            const int k4 = fi & 3;           // f4 within 16-wide k chunk
            return __ldg(reinterpret_cast<const float4*>(w_proj) + c * 64 + kc * 4 + k4);
        };
        float4 q0 = wproj_f4(g0, 0), q1 = wproj_f4(g1, 0),
               q2 = wproj_f4(g2, 0), q3 = wproj_f4(g3, 0);

        for (int kc = 0; kc < 16; kc++) {
            {
                const int cs[4]  = { g0 >> 2, g1 >> 2, g2 >> 2, g3 >> 2 };
                const int kks[4] = { (g0 & 3) * 4, (g1 & 3) * 4, (g2 & 3) * 4, (g3 & 3) * 4 };
                const float4 qs[4] = { q0, q1, q2, q3 };
                #pragma unroll
                for (int r = 0; r < 4; r++) {
                    sW[(kks[r] + 0) * 256 + cs[r]] = qs[r].x;
                    sW[(kks[r] + 1) * 256 + cs[r]] = qs[r].y;
                    sW[(kks[r] + 2) * 256 + cs[r]] = qs[r].z;
                    sW[(kks[r] + 3) * 256 + cs[r]] = qs[r].w;
                }
            }
            __syncthreads();
            if (kc < 15) {
                q0 = wproj_f4(g0, kc + 1); q1 = wproj_f4(g1, kc + 1);
                q2 = wproj_f4(g2, kc + 1); q3 = wproj_f4(g3, kc + 1);
            }
            #pragma unroll
            for (int kk = 0; kk < 16; kk++) {
                const float4 a = *reinterpret_cast<const float4*>(&sOutT[(kc * 16 + kk) * 64 + t0]);
                const float av[4] = { a.x, a.y, a.z, a.w };
                #pragma unroll
                for (int u = 0; u < 4; u++) {
                    const float4 bq = *reinterpret_cast<const float4*>(&sW[kk * 256 + u * 64 + cg * 4]);
                    const float bv[4] = { bq.x, bq.y, bq.z, bq.w };
                    #pragma unroll
                    for (int m = 0; m < 4; m++)
                        #pragma unroll
                        for (int e = 0; e < 4; e++)
                            pacc[m][u * 4 + e] += av[m] * bv[e];
                }
            }
            __syncthreads();
        }

        // bias + stage into sY (reuse sXT region), then coalesced global write
        float* sY = sXT;
        #pragma unroll
        for (int u = 0; u < 4; u++) {
            const int c0 = u * 64 + cg * 4;
            const float4 bb = *reinterpret_cast<const float4*>(&b_proj[c0]);
            #pragma unroll
            for (int m = 0; m < 4; m++) {
                float4 o;
                o.x = pacc[m][u * 4 + 0] + bb.x;
                o.y = pacc[m][u * 4 + 1] + bb.y;
                o.z = pacc[m][u * 4 + 2] + bb.z;
                o.w = pacc[m][u * 4 + 3] + bb.w;
                *reinterpret_cast<float4*>(&sY[(t0 + m) * 256 + c0]) = o;
            }
        }
        __syncthreads();

        {
            const int t = tid >> 2;
            const int p = tid & 3;
            const long long roff =
                (((long long)(b * 192 + wh * 8 + (t >> 3))) * 192 + (ww * 8 + (t & 7))) * 256;
            float4* gy = reinterpret_cast<float4*>(out + roff);
            const float4* sy = reinterpret_cast<const float4*>(&sY[t * 256]);
            #pragma unroll
            for (int u = 0; u < 16; u++) gy[p * 16 + u] = sy[p * 16 + u];
        }
    }
}

extern "C" void kernel_launch(void* const* d_in, const int* in_sizes, int n_in,
                              void* d_out, int out_size)
{
    const float* x      = (const float*)d_in[0];
    const float* w_qkv  = (const float*)d_in[1];
    const float* b_qkv  = (const float*)d_in[2];
    const float* w_proj = (const float*)d_in[3];
    const float* b_proj = (const float*)d_in[4];
    float* out = (float*)d_out;

    (void)in_sizes; (void)n_in; (void)out_size;

    cudaFuncSetAttribute(win_mhsa_fp32_kernel,
                         cudaFuncAttributeMaxDynamicSharedMemorySize, SMEM_BYTES);
    win_mhsa_fp32_kernel<<<NWIN_TOTAL, 256, SMEM_BYTES>>>(x, w_qkv, b_qkv, w_proj, b_proj, out);
}

// round 7
// speedup vs baseline: 1.6924x; 1.6924x over previous
#include <cuda_runtime.h>
#include <cuda_bf16.h>
#include <cstdint>

// LocalAttention2D: windowed MHSA. GEMMs on mma.sync bf16 (hi/lo split, 3-term,
// fp32 accumulate), attention in fp32 SIMT. One window (64 tokens) per CTA.
// grid=4608, block=256 (8 warps). Compiles for plain sm_100 (no tcgen05).

#define NWIN 4608

// ---- SMEM byte layout ----
#define XP_B     0        // X A-frag pack: [2 plane][4 mt][16 kt][32 lane][16B] = 65536
#define WB_B     65536    // GEMM1 W chunk double buffer 2x24576; reused for Wproj pack 32768
#define OP_B     114688   // O A-frag pack: [2 plane][4 mt][2 kt][32][16B] = 8192
#define SQT_B    122880   // [32][64] f32
#define SKT_B    131072   // [32][64] f32
#define SV_B     139264   // [64][34] f32 = 8704
#define SS_B     147968   // [64][68] f32 = 17408  (S, then aliased P^T)
#define SBIAS_B  165376   // 96 f32
#define SBIASP_B 165760   // 256 f32
#define SMEM_TOTAL 166784

__device__ __forceinline__ void mma16816(float* d, const uint4 a, const uint2 b) {
    asm volatile(
        "mma.sync.aligned.m16n8k16.row.col.f32.bf16.bf16.f32 "
        "{%0,%1,%2,%3}, {%4,%5,%6,%7}, {%8,%9}, {%0,%1,%2,%3};\n"
        : "+f"(d[0]), "+f"(d[1]), "+f"(d[2]), "+f"(d[3])
        : "r"(a.x), "r"(a.y), "r"(a.z), "r"(a.w), "r"(b.x), "r"(b.y));
}

// pack two floats into bf16x2 hi-plane and lo-plane words (lo = residual)
__device__ __forceinline__ void split2(float a, float b, uint32_t& hi, uint32_t& lo) {
    __nv_bfloat16 ha = __float2bfloat16(a), hb = __float2bfloat16(b);
    float ra = a - __bfloat162float(ha), rb = b - __bfloat162float(hb);
    __nv_bfloat16 la = __float2bfloat16(ra), lb = __float2bfloat16(rb);
    hi = (uint32_t)__bfloat16_as_ushort(ha) | ((uint32_t)__bfloat16_as_ushort(hb) << 16);
    lo = (uint32_t)__bfloat16_as_ushort(la) | ((uint32_t)__bfloat16_as_ushort(lb) << 16);
}

__device__ __forceinline__ int row_gbase(int win, int tok) {
    const int b  = win / 576;
    const int wh = (win % 576) / 24;
    const int ww = win % 24;
    return ((b * 192 + wh * 8 + (tok >> 3)) * 192 + (ww * 8 + (tok & 7))) * 256;
}

__global__ __launch_bounds__(256, 1)
void win_mhsa_mma_kernel(const float* __restrict__ x,
                         const float* __restrict__ w_qkv,
                         const float* __restrict__ b_qkv,
                         const float* __restrict__ w_proj,
                         const float* __restrict__ b_proj,
                         float* __restrict__ out)
{
    extern __shared__ char smc[];
    float* sQT    = (float*)(smc + SQT_B);
    float* sKT    = (float*)(smc + SKT_B);
    float* sV     = (float*)(smc + SV_B);
    float* sS     = (float*)(smc + SS_B);
    float* sBias  = (float*)(smc + SBIAS_B);
    float* sBiasP = (float*)(smc + SBIASP_B);

    const int tid  = threadIdx.x;
    const int wid  = tid >> 5;
    const int lane = tid & 31;
    const int win  = blockIdx.x;
    const float QSCALE = 0.17677669529663689f;   // 32^-0.5

    sBiasP[tid] = __ldg(&b_proj[tid]);

    // ---------------- X window -> A-fragment pack (hi/lo bf16) ----------------
    {
        const int row = tid >> 2, p = tid & 3;
        const float4* gx = reinterpret_cast<const float4*>(x + row_gbase(win, row));
        const int mt = row >> 4, rin = row & 15, g = rin & 7, rh = rin >> 3;
        #pragma unroll
        for (int u = 0; u < 16; u++) {
            const int k4 = p * 16 + u;
            const float4 v = __ldg(&gx[k4]);
            const int ktile = k4 >> 2;
            const int cpair = (k4 & 3) * 2;
            const float e[4] = { v.x, v.y, v.z, v.w };
            #pragma unroll
            for (int pr = 0; pr < 2; pr++) {
                const int cp = cpair + pr, c8 = cp >> 2, cc = cp & 3;
                const int laneX = g * 4 + cc, slot = rh + 2 * c8;
                uint32_t hi, lo;
                split2(e[pr * 2], e[pr * 2 + 1], hi, lo);
                char* base = smc + XP_B + (((mt * 16 + ktile) * 32 + laneX) << 4) + slot * 4;
                *reinterpret_cast<uint32_t*>(base)         = hi;
                *reinterpret_cast<uint32_t*>(base + 32768) = lo;
            }
        }
    }
    __syncthreads();

    const int mw = wid & 3;      // M-tile (16 tokens)
    const int nh = wid >> 2;     // N-half

    float acc2[16][4];
    #pragma unroll
    for (int i = 0; i < 16; i++)
        #pragma unroll
        for (int j = 0; j < 4; j++) acc2[i][j] = 0.0f;

    const float4* wq4 = reinterpret_cast<const float4*>(w_qkv);
    const float4* wp4 = reinterpret_cast<const float4*>(w_proj);

    for (int h = 0; h < 8; h++) {
        if (tid < 96) sBias[tid] = __ldg(&b_qkv[(tid >> 5) * 256 + h * 32 + (tid & 31)]);

        // ============ GEMM1: QKV_h[64,96] = X[64,256] @ Wh^T ============
        float acc1[6][4];
        #pragma unroll
        for (int i = 0; i < 6; i++)
            #pragma unroll
            for (int j = 0; j < 4; j++) acc1[i][j] = 0.0f;

        float4 pf[6];
        #pragma unroll
        for (int j = 0; j < 6; j++) {
            const int fi = tid + 256 * j;
            const int n = fi >> 4, k4 = fi & 15;
            const int grow = (n >> 5) * 256 + h * 32 + (n & 31);
            pf[j] = __ldg(&wq4[grow * 64 + k4]);
        }

        for (int ck = 0; ck < 4; ck++) {
            char* buf = smc + WB_B + (ck & 1) * 24576;
            #pragma unroll
            for (int j = 0; j < 6; j++) {
                const int fi = tid + 256 * j;
                const int n = fi >> 4, k4 = fi & 15;
                const int nt = n >> 3, nr = n & 7;
                const int ktile = k4 >> 2, cpair = (k4 & 3) * 2;
                const float e[4] = { pf[j].x, pf[j].y, pf[j].z, pf[j].w };
                #pragma unroll
                for (int pr = 0; pr < 2; pr++) {
                    const int cp = cpair + pr, c8 = cp >> 2, cc = cp & 3;
                    const int laneW = nr * 4 + cc;
                    uint32_t hi, lo;
                    split2(e[pr * 2], e[pr * 2 + 1], hi, lo);
                    char* dst = buf + (((nt * 4 + ktile) * 32 + laneW) << 3) + c8 * 4;
                    *reinterpret_cast<uint32_t*>(dst)         = hi;
                    *reinterpret_cast<uint32_t*>(dst + 12288) = lo;
                }
            }
            __syncthreads();
            if (ck < 3) {
                #pragma unroll
                for (int j = 0; j < 6; j++) {
                    const int fi = tid + 256 * j;
                    const int n = fi >> 4, k4 = fi & 15;
                    const int grow = (n >> 5) * 256 + h * 32 + (n & 31);
                    pf[j] = __ldg(&wq4[grow * 64 + (ck + 1) * 16 + k4]);
                }
            }
            #pragma unroll
            for (int kt = 0; kt < 4; kt++) {
                const char* ab = smc + XP_B + (((mw * 16 + ck * 4 + kt) * 32 + lane) << 4);
                const uint4 Ah = *reinterpret_cast<const uint4*>(ab);
                const uint4 Al = *reinterpret_cast<const uint4*>(ab + 32768);
                #pragma unroll
                for (int nt = 0; nt < 6; nt++) {
                    const char* bb = buf + ((((nh * 6 + nt) * 4 + kt) * 32 + lane) << 3);
                    const uint2 Bh = *reinterpret_cast<const uint2*>(bb);
                    const uint2 Bl = *reinterpret_cast<const uint2*>(bb + 12288);
                    mma16816(acc1[nt], Ah, Bh);
                    mma16816(acc1[nt], Ah, Bl);
                    mma16816(acc1[nt], Al, Bh);
                }
            }
        }

        // scatter QKV (+bias) to attention layouts
        {
            const int g = lane >> 2, c = (lane & 3) * 2;
            #pragma unroll
            for (int nt = 0; nt < 6; nt++) {
                const int colb = (nh * 6 + nt) * 8 + c;
                #pragma unroll
                for (int e = 0; e < 4; e++) {
                    const int col = colb + (e & 1);
                    const int tok = mw * 16 + g + (e >> 1) * 8;
                    const float v = acc1[nt][e] + sBias[col];
                    if (col < 32)       sQT[col * 64 + tok] = v * QSCALE;
                    else if (col < 64)  sKT[(col - 32) * 64 + tok] = v;
                    else                sV[tok * 34 + (col - 64)] = v;
                }
            }
        }
        __syncthreads();

        // stage Wproj head slice -> B-frag pack (hi/lo) in WB region
        #pragma unroll
        for (int j = 0; j < 8; j++) {
            const int fi = tid + 256 * j;
            const int c = fi >> 3, k4 = fi & 7;
            const float4 v = __ldg(&wp4[c * 64 + h * 8 + k4]);
            const int nt = c >> 3, nr = c & 7;
            const int ktile = k4 >> 2, cpair = (k4 & 3) * 2;
            const float e[4] = { v.x, v.y, v.z, v.w };
            #pragma unroll
            for (int pr = 0; pr < 2; pr++) {
                const int cp = cpair + pr, c8 = cp >> 2, cc = cp & 3;
                const int laneW = nr * 4 + cc;
                uint32_t hi, lo;
                split2(e[pr * 2], e[pr * 2 + 1], hi, lo);
                char* dst = smc + WB_B + (((nt * 2 + ktile) * 32 + laneW) << 3) + c8 * 4;
                *reinterpret_cast<uint32_t*>(dst)         = hi;
                *reinterpret_cast<uint32_t*>(dst + 16384) = lo;
            }
        }

        // ============ attention (fp32 SIMT, verified R3 code) ============
        const int tg = tid >> 4, cg = tid & 15;
        const int t0 = tg * 4, j0 = cg * 4, d0 = cg * 2;

        {   // S = Q K^T
            float sacc[4][4];
            #pragma unroll
            for (int m = 0; m < 4; m++)
                #pragma unroll
                for (int n = 0; n < 4; n++) sacc[m][n] = 0.0f;
            #pragma unroll
            for (int d = 0; d < 32; d++) {
                const float4 qa = *reinterpret_cast<const float4*>(&sQT[d * 64 + t0]);
                const float4 kb = *reinterpret_cast<const float4*>(&sKT[d * 64 + j0]);
                const float qv[4] = { qa.x, qa.y, qa.z, qa.w };
                const float kv[4] = { kb.x, kb.y, kb.z, kb.w };
                #pragma unroll
                for (int m = 0; m < 4; m++)
                    #pragma unroll
                    for (int n = 0; n < 4; n++)
                        sacc[m][n] += qv[m] * kv[n];
            }
            #pragma unroll
            for (int m = 0; m < 4; m++)
                *reinterpret_cast<float4*>(&sS[(t0 + m) * 68 + j0]) =
                    make_float4(sacc[m][0], sacc[m][1], sacc[m][2], sacc[m][3]);
        }
        __syncthreads();

        {   // softmax rows -> P^T (aliased buffer)
            const int r = tid >> 2, p = tid & 3;
            float v[16];
            const float* row = &sS[r * 68 + p * 16];
            #pragma unroll
            for (int u = 0; u < 4; u++) {
                const float4 f = *reinterpret_cast<const float4*>(row + u * 4);
                v[u * 4 + 0] = f.x; v[u * 4 + 1] = f.y;
                v[u * 4 + 2] = f.z; v[u * 4 + 3] = f.w;
            }
            float mx = v[0];
            #pragma unroll
            for (int i = 1; i < 16; i++) mx = fmaxf(mx, v[i]);
            mx = fmaxf(mx, __shfl_xor_sync(0xffffffffu, mx, 1));
            mx = fmaxf(mx, __shfl_xor_sync(0xffffffffu, mx, 2));
            float sum = 0.0f;
            #pragma unroll
            for (int i = 0; i < 16; i++) { v[i] = __expf(v[i] - mx); sum += v[i]; }
            sum += __shfl_xor_sync(0xffffffffu, sum, 1);
            sum += __shfl_xor_sync(0xffffffffu, sum, 2);
            const float inv = 1.0f / sum;
            __syncthreads();   // all S reads done before aliased P^T writes
            #pragma unroll
            for (int i = 0; i < 16; i++) sS[(p * 16 + i) * 68 + r] = v[i] * inv;
        }
        __syncthreads();

        {   // O = P V -> OPack (A-frag hi/lo)
            float oacc[4][2];
            #pragma unroll
            for (int m = 0; m < 4; m++) { oacc[m][0] = 0.0f; oacc[m][1] = 0.0f; }
            #pragma unroll 8
            for (int j = 0; j < 64; j++) {
                const float4 pa = *reinterpret_cast<const float4*>(&sS[j * 68 + t0]);
                const float2 vb = *reinterpret_cast<const float2*>(&sV[j * 34 + d0]);
                const float pv[4] = { pa.x, pa.y, pa.z, pa.w };
                #pragma unroll
                for (int m = 0; m < 4; m++) {
                    oacc[m][0] += pv[m] * vb.x;
                    oacc[m][1] += pv[m] * vb.y;
                }
            }
            const int ktile = cg >> 3, cpr = cg & 7;
            const int c8 = cpr >> 2, cc = cpr & 3;
            #pragma unroll
            for (int m = 0; m < 4; m++) {
                const int r = t0 + m;
                const int mt = r >> 4, rin = r & 15, g = rin & 7, rh = rin >> 3;
                const int laneO = g * 4 + cc, slot = rh + 2 * c8;
                uint32_t hi, lo;
                split2(oacc[m][0], oacc[m][1], hi, lo);
                char* base = smc + OP_B + (((mt * 2 + ktile) * 32 + laneO) << 4) + slot * 4;
                *reinterpret_cast<uint32_t*>(base)        = hi;
                *reinterpret_cast<uint32_t*>(base + 4096) = lo;
            }
        }
        __syncthreads();

        // ============ GEMM2: Y += O_h @ Wproj_h^T (accumulate in regs) ============
        #pragma unroll
        for (int kt = 0; kt < 2; kt++) {
            const char* ab = smc + OP_B + (((mw * 2 + kt) * 32 + lane) << 4);
            const uint4 Ah = *reinterpret_cast<const uint4*>(ab);
            const uint4 Al = *reinterpret_cast<const uint4*>(ab + 4096);
            #pragma unroll
            for (int nt = 0; nt < 16; nt++) {
                const char* bb = smc + WB_B + ((((nh * 16 + nt) * 2 + kt) * 32 + lane) << 3);
                const uint2 Bh = *reinterpret_cast<const uint2*>(bb);
                const uint2 Bl = *reinterpret_cast<const uint2*>(bb + 16384);
                mma16816(acc2[nt], Ah, Bh);
                mma16816(acc2[nt], Ah, Bl);
                mma16816(acc2[nt], Al, Bh);
            }
        }
        __syncthreads();
    } // heads

    // ---------------- epilogue: Y + b_proj -> global ----------------
    {
        const int g = lane >> 2, c = (lane & 3) * 2;
        const int tok0 = mw * 16 + g, tok1 = tok0 + 8;
        float* g0 = out + row_gbase(win, tok0);
        float* g1 = out + row_gbase(win, tok1);
        #pragma unroll
        for (int nt = 0; nt < 16; nt++) {
            const int colb = (nh * 16 + nt) * 8 + c;
            const float b0 = sBiasP[colb], b1 = sBiasP[colb + 1];
            float2 v0 = make_float2(acc2[nt][0] + b0, acc2[nt][1] + b1);
            float2 v1 = make_float2(acc2[nt][2] + b0, acc2[nt][3] + b1);
            *reinterpret_cast<float2*>(g0 + colb) = v0;
            *reinterpret_cast<float2*>(g1 + colb) = v1;
        }
    }
}

extern "C" void kernel_launch(void* const* d_in, const int* in_sizes, int n_in,
                              void* d_out, int out_size)
{
    const float* x      = (const float*)d_in[0];
    const float* w_qkv  = (const float*)d_in[1];
    const float* b_qkv  = (const float*)d_in[2];
    const float* w_proj = (const float*)d_in[3];
    const float* b_proj = (const float*)d_in[4];
    float* out = (float*)d_out;
    (void)in_sizes; (void)n_in; (void)out_size;

    cudaFuncSetAttribute(win_mhsa_mma_kernel,
                         cudaFuncAttributeMaxDynamicSharedMemorySize, SMEM_TOTAL);
    win_mhsa_mma_kernel<<<NWIN, 256, SMEM_TOTAL>>>(x, w_qkv, b_qkv, w_proj, b_proj, out);
}

// round 8
// speedup vs baseline: 2.0943x; 1.2375x over previous
#include <cuda_runtime.h>
#include <cuda_bf16.h>
#include <cstdint>

// LocalAttention2D: windowed MHSA. GEMMs on mma.sync bf16 (hi/lo split, 3-term,
// fp32 accumulate), attention in fp32 SIMT. One window (64 tokens) per CTA.
// Weights pre-packed into fragment-layout bf16 hi/lo planes in global memory
// by tiny pre-kernels (L2-resident, shared by all CTAs).
// grid=4608, block=256 (8 warps). Plain sm_100 compatible (no tcgen05).

#define NWIN 4608

// ---- SMEM byte layout ----
#define XP_B     0        // X A-frag pack: [2 plane][4 mt][16 kt][32 lane][16B] = 65536
#define OP_B     65536    // O A-frag pack: [2 plane][4 mt][2 kt][32][16B] = 8192
#define SQT_B    73728    // [32][64] f32
#define SKT_B    81920    // [32][64] f32
#define SV_B     90112    // [64][34] f32 = 8704
#define SS_B     98816    // [64][68] f32 = 17408 (S, then aliased P^T)
#define SBIAS_B  116224   // 96 f32
#define SBIASP_B 116608   // 256 f32
#define SMEM_TOTAL 117632

// ---- global packed weight buffers (B-fragment layout, bf16 hi/lo planes) ----
// gW1: w_qkv  [((h*12+nt)*16+kt)*32+lane] -> uint2 {k0 pair, k0+8 pair}
// gW2: w_proj [((h*32+nt)*2+kt)*32+lane]
__device__ uint2 gW1h[8 * 12 * 16 * 32];
__device__ uint2 gW1l[8 * 12 * 16 * 32];
__device__ uint2 gW2h[8 * 32 * 2 * 32];
__device__ uint2 gW2l[8 * 32 * 2 * 32];

__device__ __forceinline__ void mma16816(float* d, const uint4 a, const uint2 b) {
    asm volatile(
        "mma.sync.aligned.m16n8k16.row.col.f32.bf16.bf16.f32 "
        "{%0,%1,%2,%3}, {%4,%5,%6,%7}, {%8,%9}, {%0,%1,%2,%3};\n"
        : "+f"(d[0]), "+f"(d[1]), "+f"(d[2]), "+f"(d[3])
        : "r"(a.x), "r"(a.y), "r"(a.z), "r"(a.w), "r"(b.x), "r"(b.y));
}

__device__ __forceinline__ void split2(float a, float b, uint32_t& hi, uint32_t& lo) {
    __nv_bfloat16 ha = __float2bfloat16(a), hb = __float2bfloat16(b);
    float ra = a - __bfloat162float(ha), rb = b - __bfloat162float(hb);
    __nv_bfloat16 la = __float2bfloat16(ra), lb = __float2bfloat16(rb);
    hi = (uint32_t)__bfloat16_as_ushort(ha) | ((uint32_t)__bfloat16_as_ushort(hb) << 16);
    lo = (uint32_t)__bfloat16_as_ushort(la) | ((uint32_t)__bfloat16_as_ushort(lb) << 16);
}

// ---------------- pre-pack kernels ----------------
__global__ void pack_w1_kernel(const float* __restrict__ w_qkv) {
    const int gid = blockIdx.x * 256 + threadIdx.x;     // 0..49151
    const int lane = gid & 31;
    const int kt   = (gid >> 5) & 15;
    const int nt   = (gid >> 9) % 12;
    const int h    = (gid >> 9) / 12;
    const int c    = nt * 8 + (lane >> 2);              // 0..95 within head
    const int grow = (c >> 5) * 256 + h * 32 + (c & 31);
    const int k0   = kt * 16 + (lane & 3) * 2;
    const float a0 = w_qkv[grow * 256 + k0],     a1 = w_qkv[grow * 256 + k0 + 1];
    const float b0 = w_qkv[grow * 256 + k0 + 8], b1 = w_qkv[grow * 256 + k0 + 9];
    uint32_t hx, lx, hy, ly;
    split2(a0, a1, hx, lx);
    split2(b0, b1, hy, ly);
    gW1h[gid] = make_uint2(hx, hy);
    gW1l[gid] = make_uint2(lx, ly);
}

__global__ void pack_w2_kernel(const float* __restrict__ w_proj) {
    const int gid = blockIdx.x * 256 + threadIdx.x;     // 0..16383
    const int lane = gid & 31;
    const int kt   = (gid >> 5) & 1;
    const int nt   = (gid >> 6) & 31;
    const int h    = gid >> 11;
    const int n    = nt * 8 + (lane >> 2);              // output col
    const int k    = h * 32 + kt * 16 + (lane & 3) * 2;
    const float a0 = w_proj[n * 256 + k],     a1 = w_proj[n * 256 + k + 1];
    const float b0 = w_proj[n * 256 + k + 8], b1 = w_proj[n * 256 + k + 9];
    uint32_t hx, lx, hy, ly;
    split2(a0, a1, hx, lx);
    split2(b0, b1, hy, ly);
    gW2h[gid] = make_uint2(hx, hy);
    gW2l[gid] = make_uint2(lx, ly);
}

__device__ __forceinline__ int row_gbase(int win, int tok) {
    const int b  = win / 576;
    const int wh = (win % 576) / 24;
    const int ww = win % 24;
    return ((b * 192 + wh * 8 + (tok >> 3)) * 192 + (ww * 8 + (tok & 7))) * 256;
}

__global__ __launch_bounds__(256, 1)
void win_mhsa_mma_kernel(const float* __restrict__ x,
                         const float* __restrict__ b_qkv,
                         const float* __restrict__ b_proj,
                         float* __restrict__ out)
{
    extern __shared__ char smc[];
    float* sQT    = (float*)(smc + SQT_B);
    float* sKT    = (float*)(smc + SKT_B);
    float* sV     = (float*)(smc + SV_B);
    float* sS     = (float*)(smc + SS_B);
    float* sBias  = (float*)(smc + SBIAS_B);
    float* sBiasP = (float*)(smc + SBIASP_B);

    const int tid  = threadIdx.x;
    const int wid  = tid >> 5;
    const int lane = tid & 31;
    const int win  = blockIdx.x;
    const float QSCALE = 0.17677669529663689f;   // 32^-0.5

    sBiasP[tid] = __ldg(&b_proj[tid]);

    // ---------------- X window -> A-fragment pack (hi/lo bf16) ----------------
    {
        const int row = tid >> 2, p = tid & 3;
        const float4* gx = reinterpret_cast<const float4*>(x + row_gbase(win, row));
        const int mt = row >> 4, rin = row & 15, g = rin & 7, rh = rin >> 3;
        #pragma unroll
        for (int u = 0; u < 16; u++) {
            const int k4 = p * 16 + u;
            const float4 v = __ldg(&gx[k4]);
            const int ktile = k4 >> 2;
            const int cpair = (k4 & 3) * 2;
            const float e[4] = { v.x, v.y, v.z, v.w };
            #pragma unroll
            for (int pr = 0; pr < 2; pr++) {
                const int cp = cpair + pr, c8 = cp >> 2, cc = cp & 3;
                const int laneX = g * 4 + cc, slot = rh + 2 * c8;
                uint32_t hi, lo;
                split2(e[pr * 2], e[pr * 2 + 1], hi, lo);
                char* base = smc + XP_B + (((mt * 16 + ktile) * 32 + laneX) << 4) + slot * 4;
                *reinterpret_cast<uint32_t*>(base)         = hi;
                *reinterpret_cast<uint32_t*>(base + 32768) = lo;
            }
        }
    }
    __syncthreads();

    const int mw = wid & 3;      // M-tile (16 tokens)
    const int nh = wid >> 2;     // N-half

    float acc2[16][4];
    #pragma unroll
    for (int i = 0; i < 16; i++)
        #pragma unroll
        for (int j = 0; j < 4; j++) acc2[i][j] = 0.0f;

    for (int h = 0; h < 8; h++) {
        if (tid < 96) sBias[tid] = __ldg(&b_qkv[(tid >> 5) * 256 + h * 32 + (tid & 31)]);

        // ============ GEMM1: QKV_h[64,96] = X[64,256] @ Wh^T ============
        float acc1[6][4];
        #pragma unroll
        for (int i = 0; i < 6; i++)
            #pragma unroll
            for (int j = 0; j < 4; j++) acc1[i][j] = 0.0f;

        {
            const uint2* w1h = gW1h + ((h * 12 + nh * 6) * 16) * 32 + lane;
            const uint2* w1l = gW1l + ((h * 12 + nh * 6) * 16) * 32 + lane;
            #pragma unroll 4
            for (int kt = 0; kt < 16; kt++) {
                const char* ab = smc + XP_B + (((mw * 16 + kt) * 32 + lane) << 4);
                const uint4 Ah = *reinterpret_cast<const uint4*>(ab);
                const uint4 Al = *reinterpret_cast<const uint4*>(ab + 32768);
                #pragma unroll
                for (int nt = 0; nt < 6; nt++) {
                    const uint2 Bh = __ldg(&w1h[(nt * 16 + kt) * 32]);
                    const uint2 Bl = __ldg(&w1l[(nt * 16 + kt) * 32]);
                    mma16816(acc1[nt], Ah, Bh);
                    mma16816(acc1[nt], Ah, Bl);
                    mma16816(acc1[nt], Al, Bh);
                }
            }
        }

        // scatter QKV (+bias) to attention layouts
        {
            const int g = lane >> 2, c = (lane & 3) * 2;
            #pragma unroll
            for (int nt = 0; nt < 6; nt++) {
                const int colb = (nh * 6 + nt) * 8 + c;
                #pragma unroll
                for (int e = 0; e < 4; e++) {
                    const int col = colb + (e & 1);
                    const int tok = mw * 16 + g + (e >> 1) * 8;
                    const float v = acc1[nt][e] + sBias[col];
                    if (col < 32)       sQT[col * 64 + tok] = v * QSCALE;
                    else if (col < 64)  sKT[(col - 32) * 64 + tok] = v;
                    else                sV[tok * 34 + (col - 64)] = v;
                }
            }
        }
        __syncthreads();

        // ============ attention (fp32 SIMT) ============
        const int tg = tid >> 4, cg = tid & 15;
        const int t0 = tg * 4, j0 = cg * 4, d0 = cg * 2;

        {   // S = Q K^T
            float sacc[4][4];
            #pragma unroll
            for (int m = 0; m < 4; m++)
                #pragma unroll
                for (int n = 0; n < 4; n++) sacc[m][n] = 0.0f;
            #pragma unroll
            for (int d = 0; d < 32; d++) {
                const float4 qa = *reinterpret_cast<const float4*>(&sQT[d * 64 + t0]);
                const float4 kb = *reinterpret_cast<const float4*>(&sKT[d * 64 + j0]);
                const float qv[4] = { qa.x, qa.y, qa.z, qa.w };
                const float kv[4] = { kb.x, kb.y, kb.z, kb.w };
                #pragma unroll
                for (int m = 0; m < 4; m++)
                    #pragma unroll
                    for (int n = 0; n < 4; n++)
                        sacc[m][n] += qv[m] * kv[n];
            }
            #pragma unroll
            for (int m = 0; m < 4; m++)
                *reinterpret_cast<float4*>(&sS[(t0 + m) * 68 + j0]) =
                    make_float4(sacc[m][0], sacc[m][1], sacc[m][2], sacc[m][3]);
        }
        __syncthreads();

        {   // softmax rows -> P^T (aliased buffer)
            const int r = tid >> 2, p = tid & 3;
            float v[16];
            const float* row = &sS[r * 68 + p * 16];
            #pragma unroll
            for (int u = 0; u < 4; u++) {
                const float4 f = *reinterpret_cast<const float4*>(row + u * 4);
                v[u * 4 + 0] = f.x; v[u * 4 + 1] = f.y;
                v[u * 4 + 2] = f.z; v[u * 4 + 3] = f.w;
            }
            float mx = v[0];
            #pragma unroll
            for (int i = 1; i < 16; i++) mx = fmaxf(mx, v[i]);
            mx = fmaxf(mx, __shfl_xor_sync(0xffffffffu, mx, 1));
            mx = fmaxf(mx, __shfl_xor_sync(0xffffffffu, mx, 2));
            float sum = 0.0f;
            #pragma unroll
            for (int i = 0; i < 16; i++) { v[i] = __expf(v[i] - mx); sum += v[i]; }
            sum += __shfl_xor_sync(0xffffffffu, sum, 1);
            sum += __shfl_xor_sync(0xffffffffu, sum, 2);
            const float inv = 1.0f / sum;
            __syncthreads();   // all S reads done before aliased P^T writes
            #pragma unroll
            for (int i = 0; i < 16; i++) sS[(p * 16 + i) * 68 + r] = v[i] * inv;
        }
        __syncthreads();

        {   // O = P V -> OPack (A-frag hi/lo)
            float oacc[4][2];
            #pragma unroll
            for (int m = 0; m < 4; m++) { oacc[m][0] = 0.0f; oacc[m][1] = 0.0f; }
            #pragma unroll 8
            for (int j = 0; j < 64; j++) {
                const float4 pa = *reinterpret_cast<const float4*>(&sS[j * 68 + t0]);
                const float2 vb = *reinterpret_cast<const float2*>(&sV[j * 34 + d0]);
                const float pv[4] = { pa.x, pa.y, pa.z, pa.w };
                #pragma unroll
                for (int m = 0; m < 4; m++) {
                    oacc[m][0] += pv[m] * vb.x;
                    oacc[m][1] += pv[m] * vb.y;
                }
            }
            const int ktile = cg >> 3, cpr = cg & 7;
            const int c8 = cpr >> 2, cc = cpr & 3;
            #pragma unroll
            for (int m = 0; m < 4; m++) {
                const int r = t0 + m;
                const int mt = r >> 4, rin = r & 15, g = rin & 7, rh = rin >> 3;
                const int laneO = g * 4 + cc, slot = rh + 2 * c8;
                uint32_t hi, lo;
                split2(oacc[m][0], oacc[m][1], hi, lo);
                char* base = smc + OP_B + (((mt * 2 + ktile) * 32 + laneO) << 4) + slot * 4;
                *reinterpret_cast<uint32_t*>(base)        = hi;
                *reinterpret_cast<uint32_t*>(base + 4096) = lo;
            }
        }
        __syncthreads();

        // ============ GEMM2: Y += O_h @ Wproj_h^T (reg accumulate) ============
        {
            const uint2* w2h = gW2h + ((h * 32 + nh * 16) * 2) * 32 + lane;
            const uint2* w2l = gW2l + ((h * 32 + nh * 16) * 2) * 32 + lane;
            #pragma unroll
            for (int kt = 0; kt < 2; kt++) {
                const char* ab = smc + OP_B + (((mw * 2 + kt) * 32 + lane) << 4);
                const uint4 Ah = *reinterpret_cast<const uint4*>(ab);
                const uint4 Al = *reinterpret_cast<const uint4*>(ab + 4096);
                #pragma unroll
                for (int nt = 0; nt < 16; nt++) {
                    const uint2 Bh = __ldg(&w2h[(nt * 2 + kt) * 32]);
                    const uint2 Bl = __ldg(&w2l[(nt * 2 + kt) * 32]);
                    mma16816(acc2[nt], Ah, Bh);
                    mma16816(acc2[nt], Ah, Bl);
                    mma16816(acc2[nt], Al, Bh);
                }
            }
        }
        __syncthreads();   // OP free before next head's attention rewrites it
    } // heads

    // ---------------- epilogue: Y + b_proj -> global ----------------
    {
        const int g = lane >> 2, c = (lane & 3) * 2;
        const int tok0 = mw * 16 + g, tok1 = tok0 + 8;
        float* g0 = out + row_gbase(win, tok0);
        float* g1 = out + row_gbase(win, tok1);
        #pragma unroll
        for (int nt = 0; nt < 16; nt++) {
            const int colb = (nh * 16 + nt) * 8 + c;
            const float b0 = sBiasP[colb], b1 = sBiasP[colb + 1];
            float2 v0 = make_float2(acc2[nt][0] + b0, acc2[nt][1] + b1);
            float2 v1 = make_float2(acc2[nt][2] + b0, acc2[nt][3] + b1);
            *reinterpret_cast<float2*>(g0 + colb) = v0;
            *reinterpret_cast<float2*>(g1 + colb) = v1;
        }
    }
}

extern "C" void kernel_launch(void* const* d_in, const int* in_sizes, int n_in,
                              void* d_out, int out_size)
{
    const float* x      = (const float*)d_in[0];
    const float* w_qkv  = (const float*)d_in[1];
    const float* b_qkv  = (const float*)d_in[2];
    const float* w_proj = (const float*)d_in[3];
    const float* b_proj = (const float*)d_in[4];
    float* out = (float*)d_out;
    (void)in_sizes; (void)n_in; (void)out_size;

    pack_w1_kernel<<<192, 256>>>(w_qkv);
    pack_w2_kernel<<<64, 256>>>(w_proj);

    cudaFuncSetAttribute(win_mhsa_mma_kernel,
                         cudaFuncAttributeMaxDynamicSharedMemorySize, SMEM_TOTAL);
    win_mhsa_mma_kernel<<<NWIN, 256, SMEM_TOTAL>>>(x, b_qkv, b_proj, out);
}